// round 1
// baseline (speedup 1.0000x reference)
#include <cuda_runtime.h>
#include <math.h>

// Problem dims (fixed by the dataset)
#define KB 4
#define KS 2048
#define KD 4096
#define KI 11008
#define KM (KB * KS)   // 8192 tokens

// Scratch for h = silu(gate)*up, fp32 [M, I] = 360.7 MB (allowed: __device__ global)
__device__ float g_h[(size_t)KM * KI];

// ---------------------------------------------------------------------------
// K1: fused gate/up GEMM + SiLU*mul
//   h[m, n] = silu((x[m,:] . gw[n,:]) * gs) * ((x[m,:] . uw[n,:]) * us)
// Tile: BM=64 (m), BN=128 (n over I), BK=32 (k over D). 256 threads,
// thread tile 4x8 per matrix (dual accumulators = 64 regs).
// ---------------------------------------------------------------------------
__global__ void __launch_bounds__(256, 2)
k1_gate_up(const float* __restrict__ x,
           const int*   __restrict__ gw,
           const float* __restrict__ gs_p,
           const int*   __restrict__ uw,
           const float* __restrict__ us_p)
{
    __shared__ float As[32][66];    // x tile, transposed [k][m], pad 66 -> conflict-free-ish
    __shared__ float Gs[32][132];   // gate w tile, [k][n], lda 132 keeps float4 align
    __shared__ float Us[32][132];   // up   w tile

    const int t  = threadIdx.x;
    const int tx = t & 15;          // 16 threads over n (8 each)
    const int ty = t >> 4;          // 16 threads over m (4 each)
    const int m0 = blockIdx.y * 64;
    const int n0 = blockIdx.x * 128;

    float ag[4][8], au[4][8];
#pragma unroll
    for (int i = 0; i < 4; ++i)
#pragma unroll
        for (int j = 0; j < 8; ++j) { ag[i][j] = 0.f; au[i][j] = 0.f; }

    const int lrow = t >> 3;        // 0..31
    const int lc   = (t & 7) << 2;  // 0,4,...,28

    for (int k0 = 0; k0 < KD; k0 += 32) {
        // x tile: 64 x 32 fp32 (2 float4 per thread)
#pragma unroll
        for (int r = 0; r < 2; ++r) {
            const int m = lrow + r * 32;
            float4 v = *(const float4*)(x + (size_t)(m0 + m) * KD + k0 + lc);
            As[lc + 0][m] = v.x;
            As[lc + 1][m] = v.y;
            As[lc + 2][m] = v.z;
            As[lc + 3][m] = v.w;
        }
        // weight tiles: 128 x 32 int32 -> fp32 (4 int4 per thread per matrix)
#pragma unroll
        for (int r = 0; r < 4; ++r) {
            const int n = lrow + r * 32;
            const size_t off = (size_t)(n0 + n) * KD + k0 + lc;
            int4 gv = *(const int4*)(gw + off);
            int4 uv = *(const int4*)(uw + off);
            Gs[lc + 0][n] = (float)gv.x;
            Gs[lc + 1][n] = (float)gv.y;
            Gs[lc + 2][n] = (float)gv.z;
            Gs[lc + 3][n] = (float)gv.w;
            Us[lc + 0][n] = (float)uv.x;
            Us[lc + 1][n] = (float)uv.y;
            Us[lc + 2][n] = (float)uv.z;
            Us[lc + 3][n] = (float)uv.w;
        }
        __syncthreads();

#pragma unroll 8
        for (int k = 0; k < 32; ++k) {
            float a[4], wg[8], wu[8];
#pragma unroll
            for (int i = 0; i < 4; ++i) a[i] = As[k][ty * 4 + i];
            *(float4*)(wg)     = *(const float4*)&Gs[k][tx * 8];
            *(float4*)(wg + 4) = *(const float4*)&Gs[k][tx * 8 + 4];
            *(float4*)(wu)     = *(const float4*)&Us[k][tx * 8];
            *(float4*)(wu + 4) = *(const float4*)&Us[k][tx * 8 + 4];
#pragma unroll
            for (int i = 0; i < 4; ++i)
#pragma unroll
                for (int j = 0; j < 8; ++j) {
                    ag[i][j] = fmaf(a[i], wg[j], ag[i][j]);
                    au[i][j] = fmaf(a[i], wu[j], au[i][j]);
                }
        }
        __syncthreads();
    }

    const float gsc = gs_p[0];
    const float usc = us_p[0];
#pragma unroll
    for (int i = 0; i < 4; ++i) {
        float o[8];
#pragma unroll
        for (int j = 0; j < 8; ++j) {
            float g = ag[i][j] * gsc;
            float s = g / (1.0f + expf(-g));   // silu
            o[j] = s * (au[i][j] * usc);
        }
        float* p = g_h + (size_t)(m0 + ty * 4 + i) * KI + n0 + tx * 8;
        *(float4*)(p)     = make_float4(o[0], o[1], o[2], o[3]);
        *(float4*)(p + 4) = make_float4(o[4], o[5], o[6], o[7]);
    }
}

// ---------------------------------------------------------------------------
// K2: down GEMM  out[m, d] = (h[m,:] . dw[d,:]) * ds
// Tile: BM=128, BN=128, BK=32. 256 threads, thread tile 8x8.
// ---------------------------------------------------------------------------
__global__ void __launch_bounds__(256, 2)
k2_down(const int*   __restrict__ dw,
        const float* __restrict__ ds_p,
        float*       __restrict__ out)
{
    __shared__ float As[32][132];
    __shared__ float Ws[32][132];

    const int t  = threadIdx.x;
    const int tx = t & 15;
    const int ty = t >> 4;
    const int m0 = blockIdx.y * 128;
    const int n0 = blockIdx.x * 128;

    float acc[8][8];
#pragma unroll
    for (int i = 0; i < 8; ++i)
#pragma unroll
        for (int j = 0; j < 8; ++j) acc[i][j] = 0.f;

    const int lrow = t >> 3;        // 0..31
    const int lc   = (t & 7) << 2;  // 0,4,...,28

    for (int k0 = 0; k0 < KI; k0 += 32) {
#pragma unroll
        for (int r = 0; r < 4; ++r) {
            const int rr = lrow + r * 32;   // 0..127
            float4 v = *(const float4*)(g_h + (size_t)(m0 + rr) * KI + k0 + lc);
            As[lc + 0][rr] = v.x;
            As[lc + 1][rr] = v.y;
            As[lc + 2][rr] = v.z;
            As[lc + 3][rr] = v.w;
            int4 w4 = *(const int4*)(dw + (size_t)(n0 + rr) * KI + k0 + lc);
            Ws[lc + 0][rr] = (float)w4.x;
            Ws[lc + 1][rr] = (float)w4.y;
            Ws[lc + 2][rr] = (float)w4.z;
            Ws[lc + 3][rr] = (float)w4.w;
        }
        __syncthreads();

#pragma unroll 8
        for (int k = 0; k < 32; ++k) {
            float a[8], w[8];
            *(float4*)(a)     = *(const float4*)&As[k][ty * 8];
            *(float4*)(a + 4) = *(const float4*)&As[k][ty * 8 + 4];
            *(float4*)(w)     = *(const float4*)&Ws[k][tx * 8];
            *(float4*)(w + 4) = *(const float4*)&Ws[k][tx * 8 + 4];
#pragma unroll
            for (int i = 0; i < 8; ++i)
#pragma unroll
                for (int j = 0; j < 8; ++j)
                    acc[i][j] = fmaf(a[i], w[j], acc[i][j]);
        }
        __syncthreads();
    }

    const float dsc = ds_p[0];
#pragma unroll
    for (int i = 0; i < 8; ++i) {
        float* p = out + (size_t)(m0 + ty * 8 + i) * KD + n0 + tx * 8;
        *(float4*)(p)     = make_float4(acc[i][0] * dsc, acc[i][1] * dsc,
                                        acc[i][2] * dsc, acc[i][3] * dsc);
        *(float4*)(p + 4) = make_float4(acc[i][4] * dsc, acc[i][5] * dsc,
                                        acc[i][6] * dsc, acc[i][7] * dsc);
    }
}

// ---------------------------------------------------------------------------
// Inputs (metadata order): x, gate_w, gate_s, up_w, up_s, down_w, down_s
// ---------------------------------------------------------------------------
extern "C" void kernel_launch(void* const* d_in, const int* in_sizes, int n_in,
                              void* d_out, int out_size)
{
    const float* x  = (const float*)d_in[0];
    const int*   gw = (const int*)  d_in[1];
    const float* gs = (const float*)d_in[2];
    const int*   uw = (const int*)  d_in[3];
    const float* us = (const float*)d_in[4];
    const int*   dw = (const int*)  d_in[5];
    const float* ds = (const float*)d_in[6];
    float* out = (float*)d_out;

    dim3 g1(KI / 128, KM / 64);    // 86 x 128
    k1_gate_up<<<g1, 256>>>(x, gw, gs, uw, us);

    dim3 g2(KD / 128, KM / 128);   // 32 x 64
    k2_down<<<g2, 256>>>(dw, ds, out);
}

// round 4
// speedup vs baseline: 14.4093x; 14.4093x over previous
#include <cuda_runtime.h>
#include <cuda_bf16.h>
#include <cstdint>
#include <math.h>

#define KD 4096
#define KI 11008
#define KM 8192

// tcgen05 is arch-specific: only present in the sm_103a compilation pass.
#if !defined(__CUDA_ARCH__) || defined(__CUDA_ARCH_FEAT_SM103_ALL)
#define TC_OK 1
#else
#define TC_OK 0
#endif

// ---------------- persistent scratch (__device__ globals; no allocs) -------
__device__ __nv_bfloat16 g_wg[(size_t)KI * KD];   // gate w bf16 [I,D]
__device__ __nv_bfloat16 g_wu[(size_t)KI * KD];   // up   w bf16 [I,D]
__device__ __nv_bfloat16 g_wd[(size_t)KD * KI];   // down w bf16 [D,I]
__device__ __nv_bfloat16 g_xh[(size_t)KM * KD];   // x hi
__device__ __nv_bfloat16 g_xl[(size_t)KM * KD];   // x lo
__device__ __nv_bfloat16 g_hh[(size_t)KM * KI];   // h hi
__device__ __nv_bfloat16 g_hl[(size_t)KM * KI];   // h lo

// ---------------- PTX helpers ----------------------------------------------
__device__ __forceinline__ uint32_t smem_u32(const void* p) {
    return (uint32_t)__cvta_generic_to_shared(p);
}
__device__ __forceinline__ void cp16(uint32_t dst, const void* src) {
    asm volatile("cp.async.cg.shared.global [%0], [%1], 16;" :: "r"(dst), "l"(src));
}
__device__ __forceinline__ void cp_commit() { asm volatile("cp.async.commit_group;"); }
__device__ __forceinline__ void cp_wait0()  { asm volatile("cp.async.wait_group 0;"); }

#if TC_OK
__device__ __forceinline__ bool elect1() {
    uint32_t p;
    asm volatile("{\n\t.reg .pred p;\n\telect.sync _|p, 0xFFFFFFFF;\n\t"
                 "selp.b32 %0, 1, 0, p;\n\t}" : "=r"(p));
    return p != 0;
}

#define TC_ALLOC(sa, n)  asm volatile("tcgen05.alloc.cta_group::1.sync.aligned.shared::cta.b32 [%0], %1;" :: "r"(sa), "r"(n) : "memory")
#define TC_DEALLOC(t, n) asm volatile("tcgen05.dealloc.cta_group::1.sync.aligned.b32 %0, %1;" :: "r"(t), "r"(n))
#define TC_RELINQ()      asm volatile("tcgen05.relinquish_alloc_permit.cta_group::1.sync.aligned;")
#define TC_COMMIT(mb)    asm volatile("tcgen05.commit.cta_group::1.mbarrier::arrive::one.shared::cluster.b64 [%0];" :: "r"(mb) : "memory")
#define TC_WAIT_LD()     asm volatile("tcgen05.wait::ld.sync.aligned;" ::: "memory")
#define TC_FENCE_AFTER() asm volatile("tcgen05.fence::after_thread_sync;" ::: "memory")
#define FENCE_ASYNC()    asm volatile("fence.proxy.async.shared::cta;" ::: "memory")
#define MBAR_INIT(a, c)  asm volatile("mbarrier.init.shared.b64 [%0], %1;" :: "r"(a), "r"(c) : "memory")

#define MBAR_WAIT(mb, ph) do {                                                    \
    uint32_t _m = (mb), _p = (uint32_t)(ph), _d;                                  \
    asm volatile("{\n\t.reg .pred p;\n\t"                                         \
        "mbarrier.try_wait.parity.acquire.cta.shared::cta.b64 p, [%1], %2;\n\t"   \
        "selp.b32 %0, 1, 0, p;\n\t}" : "=r"(_d) : "r"(_m), "r"(_p) : "memory");   \
    if (!_d) {                                                                    \
        asm volatile("{\n\t.reg .pred P1;\n\tWL_%=:\n\t"                          \
            "mbarrier.try_wait.parity.acquire.cta.shared::cta.b64 P1, [%0], %1, 0x989680;\n\t" \
            "@P1 bra.uni WD_%=;\n\tbra.uni WL_%=;\n\tWD_%=:\n\t}"                 \
            :: "r"(_m), "r"(_p) : "memory");                                      \
    }                                                                             \
} while (0)

#define LDTM32(r, ta)                                                             \
    asm volatile("tcgen05.ld.sync.aligned.32x32b.x32.b32 "                        \
        "{%0,%1,%2,%3,%4,%5,%6,%7,%8,%9,%10,%11,%12,%13,%14,%15,"                 \
        "%16,%17,%18,%19,%20,%21,%22,%23,%24,%25,%26,%27,%28,%29,%30,%31},[%32];" \
        : "=r"((r)[0]),"=r"((r)[1]),"=r"((r)[2]),"=r"((r)[3]),                    \
          "=r"((r)[4]),"=r"((r)[5]),"=r"((r)[6]),"=r"((r)[7]),                    \
          "=r"((r)[8]),"=r"((r)[9]),"=r"((r)[10]),"=r"((r)[11]),                  \
          "=r"((r)[12]),"=r"((r)[13]),"=r"((r)[14]),"=r"((r)[15]),                \
          "=r"((r)[16]),"=r"((r)[17]),"=r"((r)[18]),"=r"((r)[19]),                \
          "=r"((r)[20]),"=r"((r)[21]),"=r"((r)[22]),"=r"((r)[23]),                \
          "=r"((r)[24]),"=r"((r)[25]),"=r"((r)[26]),"=r"((r)[27]),                \
          "=r"((r)[28]),"=r"((r)[29]),"=r"((r)[30]),"=r"((r)[31])                 \
        : "r"(ta))

__device__ __forceinline__ uint64_t sdesc(uint32_t addr) {
    // SW128, version=1(Blackwell), SBO=64 (1024B row-group), LBO=1 (16B)
    return 0x4000404000010000ULL | (uint64_t)((addr >> 4) & 0x3FFF);
}

__device__ __forceinline__ void mma_ss(uint32_t d, uint64_t a, uint64_t b,
                                       uint32_t idesc, bool acc) {
    uint32_t en = acc ? 1u : 0u, z = 0u;
    asm volatile("{\n\t.reg .pred p;\n\tsetp.ne.u32 p, %5, 0;\n\t"
        "tcgen05.mma.cta_group::1.kind::f16 [%0], %1, %2, %3, {%4,%4,%4,%4}, p;\n\t}"
        :: "r"(d), "l"(a), "l"(b), "r"(idesc), "r"(z), "r"(en) : "memory");
}

// idesc: F32 accum, BF16 a/b, N=256, M=128 (cg1)
#define IDESC ((1u << 4) | (1u << 7) | (1u << 10) | ((256u / 8) << 17) | ((128u / 16) << 24))
#endif // TC_OK

// ---------------- pre-pass kernels ------------------------------------------
__global__ void __launch_bounds__(256) wconv(const int* __restrict__ w, int sel, long n4) {
    __nv_bfloat16* o = (sel == 0) ? g_wg : (sel == 1) ? g_wu : g_wd;
    long i = blockIdx.x * (long)blockDim.x + threadIdx.x;
    long stride = (long)gridDim.x * blockDim.x;
    for (; i < n4; i += stride) {
        int4 v = ((const int4*)w)[i];
        __nv_bfloat162 p0, p1;
        p0.x = __float2bfloat16((float)v.x); p0.y = __float2bfloat16((float)v.y);
        p1.x = __float2bfloat16((float)v.z); p1.y = __float2bfloat16((float)v.w);
        ((__nv_bfloat162*)o)[2 * i]     = p0;
        ((__nv_bfloat162*)o)[2 * i + 1] = p1;
    }
}

__global__ void __launch_bounds__(256) xsplit(const float* __restrict__ x, long n4) {
    long i = blockIdx.x * (long)blockDim.x + threadIdx.x;
    long stride = (long)gridDim.x * blockDim.x;
    for (; i < n4; i += stride) {
        float4 v = ((const float4*)x)[i];
        __nv_bfloat162 h0, h1, l0, l1;
        h0.x = __float2bfloat16(v.x); l0.x = __float2bfloat16(v.x - __bfloat162float(h0.x));
        h0.y = __float2bfloat16(v.y); l0.y = __float2bfloat16(v.y - __bfloat162float(h0.y));
        h1.x = __float2bfloat16(v.z); l1.x = __float2bfloat16(v.z - __bfloat162float(h1.x));
        h1.y = __float2bfloat16(v.w); l1.y = __float2bfloat16(v.w - __bfloat162float(h1.y));
        ((__nv_bfloat162*)g_xh)[2 * i] = h0; ((__nv_bfloat162*)g_xh)[2 * i + 1] = h1;
        ((__nv_bfloat162*)g_xl)[2 * i] = l0; ((__nv_bfloat162*)g_xl)[2 * i + 1] = l1;
    }
}

// ---------------- K1: fused gate+up GEMM + SiLU*mul --------------------------
// tile M=128, N=256, K-chunk 64 bf16; D_gate = tmem cols [0,256), D_up [256,512)
#define K1_NC   (KD / 64)                // 64 chunks
#define K1_SST  98304                    // per-stage smem: Ah16K Al16K Bg32K Bu32K
#define K1_SMEM (2 * K1_SST + 1024)      // +1024 for SW128 base alignment

extern __shared__ char dsm[];

__global__ void __launch_bounds__(128, 1)
k1(const float* __restrict__ gs_p, const float* __restrict__ us_p)
{
#if TC_OK
    const int t = threadIdx.x, wid = t >> 5, lane = t & 31;
    const int n0 = blockIdx.x * 256;
    const int m0 = blockIdx.y * 128;
    // SW128 swizzle atoms require a 1024B-aligned tile base (static smem
    // precedes the dynamic region, so dsm itself is only 16B-aligned).
    const uint32_t sb = (smem_u32(dsm) + 1023u) & ~1023u;

    __shared__ uint32_t s_tm[1];
    __shared__ alignas(8) uint64_t s_mb[2];

    if (wid == 0) { TC_ALLOC(smem_u32(s_tm), 512); TC_RELINQ(); }
    if (t == 0) { MBAR_INIT(smem_u32(&s_mb[0]), 1); MBAR_INIT(smem_u32(&s_mb[1]), 1); }
    __syncthreads();
    uint32_t tm;
    asm volatile("ld.shared.b32 %0, [%1];" : "=r"(tm) : "r"(smem_u32(s_tm)));

    const int c16 = t & 7;
    const int r0  = t >> 3;                       // 0..15
    const uint32_t swc = (uint32_t)((c16 ^ (r0 & 7)) * 16);
    const __nv_bfloat16* pxh = g_xh + (size_t)(m0 + r0) * KD + c16 * 8;
    const __nv_bfloat16* pxl = g_xl + (size_t)(m0 + r0) * KD + c16 * 8;
    const __nv_bfloat16* pbg = g_wg + (size_t)(n0 + r0) * KD + c16 * 8;
    const __nv_bfloat16* pbu = g_wu + (size_t)(n0 + r0) * KD + c16 * 8;
    const uint32_t mb0 = smem_u32(&s_mb[0]), mb1 = smem_u32(&s_mb[1]);

    int ph0 = 0, ph1 = 0;
    for (int c = 0; c < K1_NC; ++c) {
        const int b = c & 1;
        if (c >= 2) {
            if (b == 0) { MBAR_WAIT(mb0, ph0); ph0 ^= 1; }
            else        { MBAR_WAIT(mb1, ph1); ph1 ^= 1; }
        }
        const int k0 = c * 64;
        const uint32_t ah = sb + b * K1_SST;
        const uint32_t al = ah + 16384;
        const uint32_t bg = ah + 32768;
        const uint32_t bu = ah + 65536;
#pragma unroll
        for (int i = 0; i < 8; ++i) {             // A tiles: 128 rows
            const uint32_t d = (uint32_t)((r0 + 16 * i) * 128) + swc;
            cp16(ah + d, pxh + (size_t)(16 * i) * KD + k0);
            cp16(al + d, pxl + (size_t)(16 * i) * KD + k0);
        }
#pragma unroll
        for (int i = 0; i < 16; ++i) {            // B tiles: 256 rows
            const uint32_t d = (uint32_t)((r0 + 16 * i) * 128) + swc;
            cp16(bg + d, pbg + (size_t)(16 * i) * KD + k0);
            cp16(bu + d, pbu + (size_t)(16 * i) * KD + k0);
        }
        cp_commit(); cp_wait0();
        __syncthreads();

        if (wid == 0) {
            FENCE_ASYNC();
            if (elect1()) {
                const uint64_t da = sdesc(ah), dl = sdesc(al);
                const uint64_t dg = sdesc(bg), du = sdesc(bu);
#pragma unroll
                for (int k = 0; k < 4; ++k) {
                    const bool acc = (c > 0) || (k > 0);
                    mma_ss(tm,       da + 2 * k, dg + 2 * k, IDESC, acc);
                    mma_ss(tm + 256, da + 2 * k, du + 2 * k, IDESC, acc);
                }
#pragma unroll
                for (int k = 0; k < 4; ++k) {
                    mma_ss(tm,       dl + 2 * k, dg + 2 * k, IDESC, true);
                    mma_ss(tm + 256, dl + 2 * k, du + 2 * k, IDESC, true);
                }
                TC_COMMIT(smem_u32(&s_mb[b]));
            }
        }
    }

    // final: last chunk (c=63) used buf 1
    MBAR_WAIT(mb1, ph1);
    TC_FENCE_AFTER();

    const float gsc = gs_p[0], usc = us_p[0];
    const int m = m0 + wid * 32 + lane;
#pragma unroll 1
    for (int cb = 0; cb < 8; ++cb) {
        uint32_t rg[32], ru[32];
        LDTM32(rg, tm + cb * 32);
        LDTM32(ru, tm + 256 + cb * 32);
        TC_WAIT_LD();
        alignas(16) ushort oh[32], ol[32];
#pragma unroll
        for (int j = 0; j < 32; ++j) {
            const float g = __uint_as_float(rg[j]) * gsc;
            const float u = __uint_as_float(ru[j]) * usc;
            const float v = (g / (1.0f + __expf(-g))) * u;
            const __nv_bfloat16 hh = __float2bfloat16(v);
            const __nv_bfloat16 hl = __float2bfloat16(v - __bfloat162float(hh));
            oh[j] = *(const ushort*)&hh;
            ol[j] = *(const ushort*)&hl;
        }
        const size_t off = ((size_t)m * KI + n0 + cb * 32) * 2;   // bytes
#pragma unroll
        for (int q = 0; q < 4; ++q) {
            *(uint4*)((char*)g_hh + off + q * 16) = *(uint4*)&oh[q * 8];
            *(uint4*)((char*)g_hl + off + q * 16) = *(uint4*)&ol[q * 8];
        }
    }
    __syncthreads();
    if (wid == 0) TC_DEALLOC(tm, 512);

#else  // ---------------- SIMT fallback (non-103a pass; never runs on GB300) ---
    const int t = threadIdx.x;
    const int n0 = blockIdx.x * 256;
    const int m0 = blockIdx.y * 128;
    float* sA = (float*)dsm;                  // [32][132]
    float* sB = (float*)(dsm + 32 * 132 * 4); // [32][68]
    const float gsc = gs_p[0], usc = us_p[0];
    const int tx = t & 7, ty = t >> 3;        // 8 x 16
    for (int ns = 0; ns < 4; ++ns) {
        const int nb = n0 + ns * 64;
        float ag[8][8], au[8][8];
#pragma unroll
        for (int i = 0; i < 8; ++i)
#pragma unroll
            for (int j = 0; j < 8; ++j) { ag[i][j] = 0.f; au[i][j] = 0.f; }
        for (int pass = 0; pass < 2; ++pass) {
            const __nv_bfloat16* W = pass ? g_wu : g_wg;
            float (*acc)[8] = pass ? au : ag;
            for (int k0 = 0; k0 < KD; k0 += 32) {
                for (int i = t; i < 128 * 32; i += 128) {
                    int r = i >> 5, c = i & 31;
                    sA[c * 132 + r] = __bfloat162float(g_xh[(size_t)(m0 + r) * KD + k0 + c])
                                    + __bfloat162float(g_xl[(size_t)(m0 + r) * KD + k0 + c]);
                }
                for (int i = t; i < 64 * 32; i += 128) {
                    int r = i >> 5, c = i & 31;
                    sB[c * 68 + r] = __bfloat162float(W[(size_t)(nb + r) * KD + k0 + c]);
                }
                __syncthreads();
                for (int k = 0; k < 32; ++k) {
                    float a[8], w[8];
#pragma unroll
                    for (int i = 0; i < 8; ++i) a[i] = sA[k * 132 + ty * 8 + i];
#pragma unroll
                    for (int j = 0; j < 8; ++j) w[j] = sB[k * 68 + tx * 8 + j];
#pragma unroll
                    for (int i = 0; i < 8; ++i)
#pragma unroll
                        for (int j = 0; j < 8; ++j)
                            acc[i][j] = fmaf(a[i], w[j], acc[i][j]);
                }
                __syncthreads();
            }
        }
#pragma unroll
        for (int i = 0; i < 8; ++i)
#pragma unroll
            for (int j = 0; j < 8; ++j) {
                const float g = ag[i][j] * gsc;
                const float v = (g / (1.0f + __expf(-g))) * (au[i][j] * usc);
                const __nv_bfloat16 hh = __float2bfloat16(v);
                const __nv_bfloat16 hl = __float2bfloat16(v - __bfloat162float(hh));
                const size_t o = (size_t)(m0 + ty * 8 + i) * KI + nb + tx * 8 + j;
                g_hh[o] = hh; g_hl[o] = hl;
            }
        __syncthreads();
    }
#endif
}

// ---------------- K2: down GEMM ----------------------------------------------
#define K2_NC   (KI / 64)                // 172 chunks
#define K2_SST  65536                    // Ah16K Al16K B32K
#define K2_SMEM (2 * K2_SST + 1024)

__global__ void __launch_bounds__(128, 1)
k2(const float* __restrict__ ds_p, float* __restrict__ out)
{
#if TC_OK
    const int t = threadIdx.x, wid = t >> 5, lane = t & 31;
    const int n0 = blockIdx.x * 256;
    const int m0 = blockIdx.y * 128;
    const uint32_t sb = (smem_u32(dsm) + 1023u) & ~1023u;

    __shared__ uint32_t s_tm[1];
    __shared__ alignas(8) uint64_t s_mb[2];

    if (wid == 0) { TC_ALLOC(smem_u32(s_tm), 512); TC_RELINQ(); }
    if (t == 0) { MBAR_INIT(smem_u32(&s_mb[0]), 1); MBAR_INIT(smem_u32(&s_mb[1]), 1); }
    __syncthreads();
    uint32_t tm;
    asm volatile("ld.shared.b32 %0, [%1];" : "=r"(tm) : "r"(smem_u32(s_tm)));

    const int c16 = t & 7;
    const int r0  = t >> 3;
    const uint32_t swc = (uint32_t)((c16 ^ (r0 & 7)) * 16);
    const __nv_bfloat16* pah = g_hh + (size_t)(m0 + r0) * KI + c16 * 8;
    const __nv_bfloat16* pal = g_hl + (size_t)(m0 + r0) * KI + c16 * 8;
    const __nv_bfloat16* pb  = g_wd + (size_t)(n0 + r0) * KI + c16 * 8;
    const uint32_t mb0 = smem_u32(&s_mb[0]), mb1 = smem_u32(&s_mb[1]);

    int ph0 = 0, ph1 = 0;
    for (int c = 0; c < K2_NC; ++c) {
        const int b = c & 1;
        if (c >= 2) {
            if (b == 0) { MBAR_WAIT(mb0, ph0); ph0 ^= 1; }
            else        { MBAR_WAIT(mb1, ph1); ph1 ^= 1; }
        }
        const int k0 = c * 64;
        const uint32_t ah = sb + b * K2_SST;
        const uint32_t al = ah + 16384;
        const uint32_t bb = ah + 32768;
#pragma unroll
        for (int i = 0; i < 8; ++i) {
            const uint32_t d = (uint32_t)((r0 + 16 * i) * 128) + swc;
            cp16(ah + d, pah + (size_t)(16 * i) * KI + k0);
            cp16(al + d, pal + (size_t)(16 * i) * KI + k0);
        }
#pragma unroll
        for (int i = 0; i < 16; ++i) {
            const uint32_t d = (uint32_t)((r0 + 16 * i) * 128) + swc;
            cp16(bb + d, pb + (size_t)(16 * i) * KI + k0);
        }
        cp_commit(); cp_wait0();
        __syncthreads();

        if (wid == 0) {
            FENCE_ASYNC();
            if (elect1()) {
                const uint64_t da = sdesc(ah), dl = sdesc(al), db = sdesc(bb);
#pragma unroll
                for (int k = 0; k < 4; ++k) {
                    const bool acc = (c > 0) || (k > 0);
                    mma_ss(tm, da + 2 * k, db + 2 * k, IDESC, acc);
                }
#pragma unroll
                for (int k = 0; k < 4; ++k)
                    mma_ss(tm, dl + 2 * k, db + 2 * k, IDESC, true);
                TC_COMMIT(smem_u32(&s_mb[b]));
            }
        }
    }

    // last chunk (c=171) -> buf 1
    MBAR_WAIT(mb1, ph1);
    TC_FENCE_AFTER();

    const float dsc = ds_p[0];
    const int m = m0 + wid * 32 + lane;
#pragma unroll 1
    for (int cb = 0; cb < 8; ++cb) {
        uint32_t r[32];
        LDTM32(r, tm + cb * 32);
        TC_WAIT_LD();
        float* p = out + (size_t)m * KD + n0 + cb * 32;
#pragma unroll
        for (int q = 0; q < 8; ++q) {
            float4 v;
            v.x = __uint_as_float(r[q * 4 + 0]) * dsc;
            v.y = __uint_as_float(r[q * 4 + 1]) * dsc;
            v.z = __uint_as_float(r[q * 4 + 2]) * dsc;
            v.w = __uint_as_float(r[q * 4 + 3]) * dsc;
            *(float4*)(p + q * 4) = v;
        }
    }
    __syncthreads();
    if (wid == 0) TC_DEALLOC(tm, 512);

#else  // ---------------- SIMT fallback ---------------------------------------
    const int t = threadIdx.x;
    const int n0 = blockIdx.x * 256;
    const int m0 = blockIdx.y * 128;
    float* sA = (float*)dsm;
    float* sB = (float*)(dsm + 32 * 132 * 4);
    const float dsc = ds_p[0];
    const int tx = t & 7, ty = t >> 3;
    for (int ns = 0; ns < 4; ++ns) {
        const int nb = n0 + ns * 64;
        float acc[8][8];
#pragma unroll
        for (int i = 0; i < 8; ++i)
#pragma unroll
            for (int j = 0; j < 8; ++j) acc[i][j] = 0.f;
        for (int k0 = 0; k0 < KI; k0 += 32) {
            for (int i = t; i < 128 * 32; i += 128) {
                int r = i >> 5, c = i & 31;
                sA[c * 132 + r] = __bfloat162float(g_hh[(size_t)(m0 + r) * KI + k0 + c])
                                + __bfloat162float(g_hl[(size_t)(m0 + r) * KI + k0 + c]);
            }
            for (int i = t; i < 64 * 32; i += 128) {
                int r = i >> 5, c = i & 31;
                sB[c * 68 + r] = __bfloat162float(g_wd[(size_t)(nb + r) * KI + k0 + c]);
            }
            __syncthreads();
            for (int k = 0; k < 32; ++k) {
                float a[8], w[8];
#pragma unroll
                for (int i = 0; i < 8; ++i) a[i] = sA[k * 132 + ty * 8 + i];
#pragma unroll
                for (int j = 0; j < 8; ++j) w[j] = sB[k * 68 + tx * 8 + j];
#pragma unroll
                for (int i = 0; i < 8; ++i)
#pragma unroll
                    for (int j = 0; j < 8; ++j)
                        acc[i][j] = fmaf(a[i], w[j], acc[i][j]);
            }
            __syncthreads();
        }
#pragma unroll
        for (int i = 0; i < 8; ++i)
#pragma unroll
            for (int j = 0; j < 8; ++j)
                out[(size_t)(m0 + ty * 8 + i) * KD + nb + tx * 8 + j] = acc[i][j] * dsc;
        __syncthreads();
    }
#endif
}

// ---------------- launch ------------------------------------------------------
extern "C" void kernel_launch(void* const* d_in, const int* in_sizes, int n_in,
                              void* d_out, int out_size)
{
    const float* x  = (const float*)d_in[0];
    const int*   gw = (const int*)  d_in[1];
    const float* gs = (const float*)d_in[2];
    const int*   uw = (const int*)  d_in[3];
    const float* us = (const float*)d_in[4];
    const int*   dw = (const int*)  d_in[5];
    const float* ds = (const float*)d_in[6];
    float* out = (float*)d_out;

    cudaFuncSetAttribute(k1, cudaFuncAttributeMaxDynamicSharedMemorySize, K1_SMEM);
    cudaFuncSetAttribute(k2, cudaFuncAttributeMaxDynamicSharedMemorySize, K2_SMEM);

    const long nw4 = (long)KI * KD / 4;     // gate/up/down all same element count
    wconv<<<4096, 256>>>(gw, 0, nw4);
    wconv<<<4096, 256>>>(uw, 1, nw4);
    wconv<<<4096, 256>>>(dw, 2, nw4);
    xsplit<<<4096, 256>>>(x, (long)KM * KD / 4);

    k1<<<dim3(KI / 256, KM / 128), 128, K1_SMEM>>>(gs, us);
    k2<<<dim3(KD / 256, KM / 128), 128, K2_SMEM>>>(ds, out);
}

// round 5
// speedup vs baseline: 17.7332x; 1.2307x over previous
#include <cuda_runtime.h>
#include <cuda_bf16.h>
#include <cstdint>
#include <math.h>

#define KD 4096
#define KI 11008
#define KM 8192

// tcgen05 is arch-specific: only present in the sm_103a compilation pass.
#if !defined(__CUDA_ARCH__) || defined(__CUDA_ARCH_FEAT_SM103_ALL)
#define TC_OK 1
#else
#define TC_OK 0
#endif

// ---------------- persistent scratch (__device__ globals; no allocs) -------
__device__ __nv_bfloat16 g_wg[(size_t)KI * KD];   // gate w bf16 [I,D]
__device__ __nv_bfloat16 g_wu[(size_t)KI * KD];   // up   w bf16 [I,D]
__device__ __nv_bfloat16 g_wd[(size_t)KD * KI];   // down w bf16 [D,I]
__device__ __nv_bfloat16 g_xh[(size_t)KM * KD];   // x hi
__device__ __nv_bfloat16 g_xl[(size_t)KM * KD];   // x lo
__device__ __nv_bfloat16 g_hh[(size_t)KM * KI];   // h hi
__device__ __nv_bfloat16 g_hl[(size_t)KM * KI];   // h lo

// ---------------- PTX helpers ----------------------------------------------
__device__ __forceinline__ uint32_t smem_u32(const void* p) {
    return (uint32_t)__cvta_generic_to_shared(p);
}
__device__ __forceinline__ void cp16(uint32_t dst, const void* src) {
    asm volatile("cp.async.cg.shared.global [%0], [%1], 16;" :: "r"(dst), "l"(src));
}
__device__ __forceinline__ void cp_commit() { asm volatile("cp.async.commit_group;"); }
__device__ __forceinline__ void cp_wait0()  { asm volatile("cp.async.wait_group 0;"); }
__device__ __forceinline__ void cp_wait1()  { asm volatile("cp.async.wait_group 1;"); }

#if TC_OK
__device__ __forceinline__ bool elect1() {
    uint32_t p;
    asm volatile("{\n\t.reg .pred p;\n\telect.sync _|p, 0xFFFFFFFF;\n\t"
                 "selp.b32 %0, 1, 0, p;\n\t}" : "=r"(p));
    return p != 0;
}

#define TC_ALLOC(sa, n)  asm volatile("tcgen05.alloc.cta_group::1.sync.aligned.shared::cta.b32 [%0], %1;" :: "r"(sa), "r"(n) : "memory")
#define TC_DEALLOC(t, n) asm volatile("tcgen05.dealloc.cta_group::1.sync.aligned.b32 %0, %1;" :: "r"(t), "r"(n))
#define TC_RELINQ()      asm volatile("tcgen05.relinquish_alloc_permit.cta_group::1.sync.aligned;")
#define TC_COMMIT(mb)    asm volatile("tcgen05.commit.cta_group::1.mbarrier::arrive::one.shared::cluster.b64 [%0];" :: "r"(mb) : "memory")
#define TC_WAIT_LD()     asm volatile("tcgen05.wait::ld.sync.aligned;" ::: "memory")
#define TC_FENCE_AFTER() asm volatile("tcgen05.fence::after_thread_sync;" ::: "memory")
#define FENCE_ASYNC()    asm volatile("fence.proxy.async.shared::cta;" ::: "memory")
#define MBAR_INIT(a, c)  asm volatile("mbarrier.init.shared.b64 [%0], %1;" :: "r"(a), "r"(c) : "memory")

#define MBAR_WAIT(mb, ph) do {                                                    \
    uint32_t _m = (mb), _p = (uint32_t)(ph), _d;                                  \
    asm volatile("{\n\t.reg .pred p;\n\t"                                         \
        "mbarrier.try_wait.parity.acquire.cta.shared::cta.b64 p, [%1], %2;\n\t"   \
        "selp.b32 %0, 1, 0, p;\n\t}" : "=r"(_d) : "r"(_m), "r"(_p) : "memory");   \
    if (!_d) {                                                                    \
        asm volatile("{\n\t.reg .pred P1;\n\tWL_%=:\n\t"                          \
            "mbarrier.try_wait.parity.acquire.cta.shared::cta.b64 P1, [%0], %1, 0x989680;\n\t" \
            "@P1 bra.uni WD_%=;\n\tbra.uni WL_%=;\n\tWD_%=:\n\t}"                 \
            :: "r"(_m), "r"(_p) : "memory");                                      \
    }                                                                             \
} while (0)

#define LDTM32(r, ta)                                                             \
    asm volatile("tcgen05.ld.sync.aligned.32x32b.x32.b32 "                        \
        "{%0,%1,%2,%3,%4,%5,%6,%7,%8,%9,%10,%11,%12,%13,%14,%15,"                 \
        "%16,%17,%18,%19,%20,%21,%22,%23,%24,%25,%26,%27,%28,%29,%30,%31},[%32];" \
        : "=r"((r)[0]),"=r"((r)[1]),"=r"((r)[2]),"=r"((r)[3]),                    \
          "=r"((r)[4]),"=r"((r)[5]),"=r"((r)[6]),"=r"((r)[7]),                    \
          "=r"((r)[8]),"=r"((r)[9]),"=r"((r)[10]),"=r"((r)[11]),                  \
          "=r"((r)[12]),"=r"((r)[13]),"=r"((r)[14]),"=r"((r)[15]),                \
          "=r"((r)[16]),"=r"((r)[17]),"=r"((r)[18]),"=r"((r)[19]),                \
          "=r"((r)[20]),"=r"((r)[21]),"=r"((r)[22]),"=r"((r)[23]),                \
          "=r"((r)[24]),"=r"((r)[25]),"=r"((r)[26]),"=r"((r)[27]),                \
          "=r"((r)[28]),"=r"((r)[29]),"=r"((r)[30]),"=r"((r)[31])                 \
        : "r"(ta))

__device__ __forceinline__ uint64_t sdesc(uint32_t addr) {
    // SW128, version=1(Blackwell), SBO=64 (1024B row-group), LBO=1 (16B)
    return 0x4000404000010000ULL | (uint64_t)((addr >> 4) & 0x3FFF);
}

__device__ __forceinline__ void mma_ss(uint32_t d, uint64_t a, uint64_t b,
                                       uint32_t idesc, bool acc) {
    uint32_t en = acc ? 1u : 0u, z = 0u;
    asm volatile("{\n\t.reg .pred p;\n\tsetp.ne.u32 p, %5, 0;\n\t"
        "tcgen05.mma.cta_group::1.kind::f16 [%0], %1, %2, %3, {%4,%4,%4,%4}, p;\n\t}"
        :: "r"(d), "l"(a), "l"(b), "r"(idesc), "r"(z), "r"(en) : "memory");
}

// idesc: F32 accum, BF16 a/b, N=256, M=128 (cg1)
#define IDESC ((1u << 4) | (1u << 7) | (1u << 10) | ((256u / 8) << 17) | ((128u / 16) << 24))
#endif // TC_OK

// ---------------- pre-pass kernels ------------------------------------------
__global__ void __launch_bounds__(256) wconv(const int* __restrict__ w, int sel, long n4) {
    __nv_bfloat16* o = (sel == 0) ? g_wg : (sel == 1) ? g_wu : g_wd;
    long i = blockIdx.x * (long)blockDim.x + threadIdx.x;
    long stride = (long)gridDim.x * blockDim.x;
    for (; i < n4; i += stride) {
        int4 v = ((const int4*)w)[i];
        __nv_bfloat162 p0, p1;
        p0.x = __float2bfloat16((float)v.x); p0.y = __float2bfloat16((float)v.y);
        p1.x = __float2bfloat16((float)v.z); p1.y = __float2bfloat16((float)v.w);
        ((__nv_bfloat162*)o)[2 * i]     = p0;
        ((__nv_bfloat162*)o)[2 * i + 1] = p1;
    }
}

__global__ void __launch_bounds__(256) xsplit(const float* __restrict__ x, long n4) {
    long i = blockIdx.x * (long)blockDim.x + threadIdx.x;
    long stride = (long)gridDim.x * blockDim.x;
    for (; i < n4; i += stride) {
        float4 v = ((const float4*)x)[i];
        __nv_bfloat162 h0, h1, l0, l1;
        h0.x = __float2bfloat16(v.x); l0.x = __float2bfloat16(v.x - __bfloat162float(h0.x));
        h0.y = __float2bfloat16(v.y); l0.y = __float2bfloat16(v.y - __bfloat162float(h0.y));
        h1.x = __float2bfloat16(v.z); l1.x = __float2bfloat16(v.z - __bfloat162float(h1.x));
        h1.y = __float2bfloat16(v.w); l1.y = __float2bfloat16(v.w - __bfloat162float(h1.y));
        ((__nv_bfloat162*)g_xh)[2 * i] = h0; ((__nv_bfloat162*)g_xh)[2 * i + 1] = h1;
        ((__nv_bfloat162*)g_xl)[2 * i] = l0; ((__nv_bfloat162*)g_xl)[2 * i + 1] = l1;
    }
}

// ---------------- K1: fused gate+up GEMM + SiLU*mul --------------------------
// tile M=128, N=256, K-chunk 64 bf16; D_gate = tmem cols [0,256), D_up [256,512)
#define K1_NC   (KD / 64)                // 64 chunks
#define K1_SST  98304                    // per-stage smem: Ah16K Al16K Bg32K Bu32K
#define K1_SMEM (2 * K1_SST + 1024)      // +1024 for SW128 base alignment

extern __shared__ char dsm[];

__global__ void __launch_bounds__(256, 1)
k1(const float* __restrict__ gs_p, const float* __restrict__ us_p)
{
#if TC_OK
    const int t = threadIdx.x, wid = t >> 5, lane = t & 31;
    const int n0 = blockIdx.x * 256;
    const int m0 = blockIdx.y * 128;
    // SW128 swizzle atoms require a 1024B-aligned tile base.
    const uint32_t sb = (smem_u32(dsm) + 1023u) & ~1023u;

    __shared__ uint32_t s_tm[1];
    __shared__ alignas(8) uint64_t s_mb[2];

    if (wid == 0) { TC_ALLOC(smem_u32(s_tm), 512); TC_RELINQ(); }
    if (t == 0) { MBAR_INIT(smem_u32(&s_mb[0]), 1); MBAR_INIT(smem_u32(&s_mb[1]), 1); }
    __syncthreads();
    uint32_t tm;
    asm volatile("ld.shared.b32 %0, [%1];" : "=r"(tm) : "r"(smem_u32(s_tm)));

    const int c16 = t & 7;
    const int r0  = t >> 3;                       // 0..31
    const uint32_t swc = (uint32_t)((c16 ^ (r0 & 7)) * 16);
    const __nv_bfloat16* pxh = g_xh + (size_t)(m0 + r0) * KD + c16 * 8;
    const __nv_bfloat16* pxl = g_xl + (size_t)(m0 + r0) * KD + c16 * 8;
    const __nv_bfloat16* pbg = g_wg + (size_t)(n0 + r0) * KD + c16 * 8;
    const __nv_bfloat16* pbu = g_wu + (size_t)(n0 + r0) * KD + c16 * 8;
    const uint32_t mb0 = smem_u32(&s_mb[0]), mb1 = smem_u32(&s_mb[1]);

    // issue loads for chunk c into buffer b
    auto issue = [&](int c, int b) {
        const int k0 = c * 64;
        const uint32_t ah = sb + b * K1_SST;
        const uint32_t al = ah + 16384;
        const uint32_t bg = ah + 32768;
        const uint32_t bu = ah + 65536;
#pragma unroll
        for (int i = 0; i < 4; ++i) {             // A: 128 rows, 32/iter
            const uint32_t d = (uint32_t)((r0 + 32 * i) * 128) + swc;
            cp16(ah + d, pxh + (size_t)(32 * i) * KD + k0);
            cp16(al + d, pxl + (size_t)(32 * i) * KD + k0);
        }
#pragma unroll
        for (int i = 0; i < 8; ++i) {             // B: 256 rows
            const uint32_t d = (uint32_t)((r0 + 32 * i) * 128) + swc;
            cp16(bg + d, pbg + (size_t)(32 * i) * KD + k0);
            cp16(bu + d, pbu + (size_t)(32 * i) * KD + k0);
        }
        cp_commit();
    };

    int ph0 = 0, ph1 = 0;
    issue(0, 0);                                  // prologue
    for (int c = 0; c < K1_NC; ++c) {
        const int b = c & 1;
        if (c + 1 < K1_NC) {
            const int nb = b ^ 1;
            if (c >= 1) {                         // MMA(c-1) owns buffer nb
                if (nb == 0) { MBAR_WAIT(mb0, ph0); ph0 ^= 1; }
                else         { MBAR_WAIT(mb1, ph1); ph1 ^= 1; }
            }
            issue(c + 1, nb);                     // prefetch BEFORE waiting
            cp_wait1();                           // chunk c landed; c+1 in flight
        } else {
            cp_wait0();
        }
        __syncthreads();

        if (wid == 0) {
            FENCE_ASYNC();
            if (elect1()) {
                const uint32_t ah = sb + b * K1_SST;
                const uint64_t da = sdesc(ah), dl = sdesc(ah + 16384);
                const uint64_t dg = sdesc(ah + 32768), du = sdesc(ah + 65536);
#pragma unroll
                for (int k = 0; k < 4; ++k) {
                    const bool acc = (c > 0) || (k > 0);
                    mma_ss(tm,       da + 2 * k, dg + 2 * k, IDESC, acc);
                    mma_ss(tm + 256, da + 2 * k, du + 2 * k, IDESC, acc);
                }
#pragma unroll
                for (int k = 0; k < 4; ++k) {
                    mma_ss(tm,       dl + 2 * k, dg + 2 * k, IDESC, true);
                    mma_ss(tm + 256, dl + 2 * k, du + 2 * k, IDESC, true);
                }
                TC_COMMIT(b == 0 ? mb0 : mb1);
            }
        }
    }

    // last chunk (c=63) used buffer 1
    MBAR_WAIT(mb1, ph1);
    TC_FENCE_AFTER();

    // epilogue: 8 warps; warp w -> m rows (w&3)*32, col half (w>>2)*128
    const float gsc = gs_p[0], usc = us_p[0];
    const int m = m0 + (wid & 3) * 32 + lane;
    const int cb0 = (wid >> 2) * 4;
#pragma unroll 1
    for (int cb = cb0; cb < cb0 + 4; ++cb) {
        uint32_t rg[32], ru[32];
        LDTM32(rg, tm + cb * 32);
        LDTM32(ru, tm + 256 + cb * 32);
        TC_WAIT_LD();
        alignas(16) ushort oh[32], ol[32];
#pragma unroll
        for (int j = 0; j < 32; ++j) {
            const float g = __uint_as_float(rg[j]) * gsc;
            const float u = __uint_as_float(ru[j]) * usc;
            const float v = (g / (1.0f + __expf(-g))) * u;
            const __nv_bfloat16 hh = __float2bfloat16(v);
            const __nv_bfloat16 hl = __float2bfloat16(v - __bfloat162float(hh));
            oh[j] = *(const ushort*)&hh;
            ol[j] = *(const ushort*)&hl;
        }
        const size_t off = ((size_t)m * KI + n0 + cb * 32) * 2;   // bytes
#pragma unroll
        for (int q = 0; q < 4; ++q) {
            *(uint4*)((char*)g_hh + off + q * 16) = *(uint4*)&oh[q * 8];
            *(uint4*)((char*)g_hl + off + q * 16) = *(uint4*)&ol[q * 8];
        }
    }
    __syncthreads();
    if (wid == 0) TC_DEALLOC(tm, 512);

#else  // ---------------- SIMT fallback (non-103a pass; never runs on GB300) ---
    const int t = threadIdx.x;
    const int n0 = blockIdx.x * 256;
    const int m0 = blockIdx.y * 128;
    float* sA = (float*)dsm;                  // [32][132]
    float* sB = (float*)(dsm + 32 * 132 * 4); // [32][68]
    const float gsc = gs_p[0], usc = us_p[0];
    const int tx = t & 7, ty = (t >> 3) & 15; // threads >=128 mirror 0..127
    for (int ns = 0; ns < 4; ++ns) {
        const int nb = n0 + ns * 64;
        float ag[8][8], au[8][8];
#pragma unroll
        for (int i = 0; i < 8; ++i)
#pragma unroll
            for (int j = 0; j < 8; ++j) { ag[i][j] = 0.f; au[i][j] = 0.f; }
        for (int pass = 0; pass < 2; ++pass) {
            const __nv_bfloat16* W = pass ? g_wu : g_wg;
            float (*acc)[8] = pass ? au : ag;
            for (int k0 = 0; k0 < KD; k0 += 32) {
                for (int i = t; i < 128 * 32; i += blockDim.x) {
                    int r = i >> 5, c = i & 31;
                    sA[c * 132 + r] = __bfloat162float(g_xh[(size_t)(m0 + r) * KD + k0 + c])
                                    + __bfloat162float(g_xl[(size_t)(m0 + r) * KD + k0 + c]);
                }
                for (int i = t; i < 64 * 32; i += blockDim.x) {
                    int r = i >> 5, c = i & 31;
                    sB[c * 68 + r] = __bfloat162float(W[(size_t)(nb + r) * KD + k0 + c]);
                }
                __syncthreads();
                for (int k = 0; k < 32; ++k) {
                    float a[8], w[8];
#pragma unroll
                    for (int i = 0; i < 8; ++i) a[i] = sA[k * 132 + ty * 8 + i];
#pragma unroll
                    for (int j = 0; j < 8; ++j) w[j] = sB[k * 68 + tx * 8 + j];
#pragma unroll
                    for (int i = 0; i < 8; ++i)
#pragma unroll
                        for (int j = 0; j < 8; ++j)
                            acc[i][j] = fmaf(a[i], w[j], acc[i][j]);
                }
                __syncthreads();
            }
        }
#pragma unroll
        for (int i = 0; i < 8; ++i)
#pragma unroll
            for (int j = 0; j < 8; ++j) {
                const float g = ag[i][j] * gsc;
                const float v = (g / (1.0f + __expf(-g))) * (au[i][j] * usc);
                const __nv_bfloat16 hh = __float2bfloat16(v);
                const __nv_bfloat16 hl = __float2bfloat16(v - __bfloat162float(hh));
                const size_t o = (size_t)(m0 + ty * 8 + i) * KI + nb + tx * 8 + j;
                g_hh[o] = hh; g_hl[o] = hl;
            }
        __syncthreads();
    }
#endif
}

// ---------------- K2: down GEMM ----------------------------------------------
#define K2_NC   (KI / 64)                // 172 chunks
#define K2_SST  65536                    // Ah16K Al16K B32K
#define K2_SMEM (2 * K2_SST + 1024)

__global__ void __launch_bounds__(256, 1)
k2(const float* __restrict__ ds_p, float* __restrict__ out)
{
#if TC_OK
    const int t = threadIdx.x, wid = t >> 5, lane = t & 31;
    const int n0 = blockIdx.x * 256;
    const int m0 = blockIdx.y * 128;
    const uint32_t sb = (smem_u32(dsm) + 1023u) & ~1023u;

    __shared__ uint32_t s_tm[1];
    __shared__ alignas(8) uint64_t s_mb[2];

    if (wid == 0) { TC_ALLOC(smem_u32(s_tm), 512); TC_RELINQ(); }
    if (t == 0) { MBAR_INIT(smem_u32(&s_mb[0]), 1); MBAR_INIT(smem_u32(&s_mb[1]), 1); }
    __syncthreads();
    uint32_t tm;
    asm volatile("ld.shared.b32 %0, [%1];" : "=r"(tm) : "r"(smem_u32(s_tm)));

    const int c16 = t & 7;
    const int r0  = t >> 3;
    const uint32_t swc = (uint32_t)((c16 ^ (r0 & 7)) * 16);
    const __nv_bfloat16* pah = g_hh + (size_t)(m0 + r0) * KI + c16 * 8;
    const __nv_bfloat16* pal = g_hl + (size_t)(m0 + r0) * KI + c16 * 8;
    const __nv_bfloat16* pb  = g_wd + (size_t)(n0 + r0) * KI + c16 * 8;
    const uint32_t mb0 = smem_u32(&s_mb[0]), mb1 = smem_u32(&s_mb[1]);

    auto issue = [&](int c, int b) {
        const int k0 = c * 64;
        const uint32_t ah = sb + b * K2_SST;
        const uint32_t al = ah + 16384;
        const uint32_t bb = ah + 32768;
#pragma unroll
        for (int i = 0; i < 4; ++i) {
            const uint32_t d = (uint32_t)((r0 + 32 * i) * 128) + swc;
            cp16(ah + d, pah + (size_t)(32 * i) * KI + k0);
            cp16(al + d, pal + (size_t)(32 * i) * KI + k0);
        }
#pragma unroll
        for (int i = 0; i < 8; ++i) {
            const uint32_t d = (uint32_t)((r0 + 32 * i) * 128) + swc;
            cp16(bb + d, pb + (size_t)(32 * i) * KI + k0);
        }
        cp_commit();
    };

    int ph0 = 0, ph1 = 0;
    issue(0, 0);
    for (int c = 0; c < K2_NC; ++c) {
        const int b = c & 1;
        if (c + 1 < K2_NC) {
            const int nb = b ^ 1;
            if (c >= 1) {
                if (nb == 0) { MBAR_WAIT(mb0, ph0); ph0 ^= 1; }
                else         { MBAR_WAIT(mb1, ph1); ph1 ^= 1; }
            }
            issue(c + 1, nb);
            cp_wait1();
        } else {
            cp_wait0();
        }
        __syncthreads();

        if (wid == 0) {
            FENCE_ASYNC();
            if (elect1()) {
                const uint32_t ah = sb + b * K2_SST;
                const uint64_t da = sdesc(ah), dl = sdesc(ah + 16384);
                const uint64_t db = sdesc(ah + 32768);
#pragma unroll
                for (int k = 0; k < 4; ++k) {
                    const bool acc = (c > 0) || (k > 0);
                    mma_ss(tm, da + 2 * k, db + 2 * k, IDESC, acc);
                }
#pragma unroll
                for (int k = 0; k < 4; ++k)
                    mma_ss(tm, dl + 2 * k, db + 2 * k, IDESC, true);
                TC_COMMIT(b == 0 ? mb0 : mb1);
            }
        }
    }

    // last chunk (c=171) -> buffer 1
    MBAR_WAIT(mb1, ph1);
    TC_FENCE_AFTER();

    const float dsc = ds_p[0];
    const int m = m0 + (wid & 3) * 32 + lane;
    const int cb0 = (wid >> 2) * 4;
#pragma unroll 1
    for (int cb = cb0; cb < cb0 + 4; ++cb) {
        uint32_t r[32];
        LDTM32(r, tm + cb * 32);
        TC_WAIT_LD();
        float* p = out + (size_t)m * KD + n0 + cb * 32;
#pragma unroll
        for (int q = 0; q < 8; ++q) {
            float4 v;
            v.x = __uint_as_float(r[q * 4 + 0]) * dsc;
            v.y = __uint_as_float(r[q * 4 + 1]) * dsc;
            v.z = __uint_as_float(r[q * 4 + 2]) * dsc;
            v.w = __uint_as_float(r[q * 4 + 3]) * dsc;
            *(float4*)(p + q * 4) = v;
        }
    }
    __syncthreads();
    if (wid == 0) TC_DEALLOC(tm, 512);

#else  // ---------------- SIMT fallback ---------------------------------------
    const int t = threadIdx.x;
    const int n0 = blockIdx.x * 256;
    const int m0 = blockIdx.y * 128;
    float* sA = (float*)dsm;
    float* sB = (float*)(dsm + 32 * 132 * 4);
    const float dsc = ds_p[0];
    const int tx = t & 7, ty = (t >> 3) & 15;
    for (int ns = 0; ns < 4; ++ns) {
        const int nb = n0 + ns * 64;
        float acc[8][8];
#pragma unroll
        for (int i = 0; i < 8; ++i)
#pragma unroll
            for (int j = 0; j < 8; ++j) acc[i][j] = 0.f;
        for (int k0 = 0; k0 < KI; k0 += 32) {
            for (int i = t; i < 128 * 32; i += blockDim.x) {
                int r = i >> 5, c = i & 31;
                sA[c * 132 + r] = __bfloat162float(g_hh[(size_t)(m0 + r) * KI + k0 + c])
                                + __bfloat162float(g_hl[(size_t)(m0 + r) * KI + k0 + c]);
            }
            for (int i = t; i < 64 * 32; i += blockDim.x) {
                int r = i >> 5, c = i & 31;
                sB[c * 68 + r] = __bfloat162float(g_wd[(size_t)(nb + r) * KI + k0 + c]);
            }
            __syncthreads();
            for (int k = 0; k < 32; ++k) {
                float a[8], w[8];
#pragma unroll
                for (int i = 0; i < 8; ++i) a[i] = sA[k * 132 + ty * 8 + i];
#pragma unroll
                for (int j = 0; j < 8; ++j) w[j] = sB[k * 68 + tx * 8 + j];
#pragma unroll
                for (int i = 0; i < 8; ++i)
#pragma unroll
                    for (int j = 0; j < 8; ++j)
                        acc[i][j] = fmaf(a[i], w[j], acc[i][j]);
            }
            __syncthreads();
        }
#pragma unroll
        for (int i = 0; i < 8; ++i)
#pragma unroll
            for (int j = 0; j < 8; ++j)
                out[(size_t)(m0 + ty * 8 + i) * KD + nb + tx * 8 + j] = acc[i][j] * dsc;
        __syncthreads();
    }
#endif
}

// ---------------- launch ------------------------------------------------------
extern "C" void kernel_launch(void* const* d_in, const int* in_sizes, int n_in,
                              void* d_out, int out_size)
{
    const float* x  = (const float*)d_in[0];
    const int*   gw = (const int*)  d_in[1];
    const float* gs = (const float*)d_in[2];
    const int*   uw = (const int*)  d_in[3];
    const float* us = (const float*)d_in[4];
    const int*   dw = (const int*)  d_in[5];
    const float* ds = (const float*)d_in[6];
    float* out = (float*)d_out;

    cudaFuncSetAttribute(k1, cudaFuncAttributeMaxDynamicSharedMemorySize, K1_SMEM);
    cudaFuncSetAttribute(k2, cudaFuncAttributeMaxDynamicSharedMemorySize, K2_SMEM);

    const long nw4 = (long)KI * KD / 4;     // gate/up/down all same element count
    wconv<<<4096, 256>>>(gw, 0, nw4);
    wconv<<<4096, 256>>>(uw, 1, nw4);
    wconv<<<4096, 256>>>(dw, 2, nw4);
    xsplit<<<4096, 256>>>(x, (long)KM * KD / 4);

    k1<<<dim3(KI / 256, KM / 128), 256, K1_SMEM>>>(gs, us);
    k2<<<dim3(KD / 256, KM / 128), 256, K2_SMEM>>>(ds, out);
}

// round 6
// speedup vs baseline: 18.3482x; 1.0347x over previous
#include <cuda_runtime.h>
#include <cuda_bf16.h>
#include <cstdint>
#include <math.h>

#define KD 4096
#define KI 11008
#define KM 8192

// tcgen05 is arch-specific: only present in the sm_103a compilation pass.
#if !defined(__CUDA_ARCH__) || defined(__CUDA_ARCH_FEAT_SM103_ALL)
#define TC_OK 1
#else
#define TC_OK 0
#endif

// ---------------- persistent scratch (__device__ globals; no allocs) -------
__device__ __nv_bfloat16 g_wg[(size_t)KI * KD];   // gate w bf16 [I,D]
__device__ __nv_bfloat16 g_wu[(size_t)KI * KD];   // up   w bf16 [I,D]
__device__ __nv_bfloat16 g_wd[(size_t)KD * KI];   // down w bf16 [D,I]
__device__ __nv_bfloat16 g_xh[(size_t)KM * KD];   // x hi
__device__ __nv_bfloat16 g_xl[(size_t)KM * KD];   // x lo
__device__ __nv_bfloat16 g_hh[(size_t)KM * KI];   // h hi
__device__ __nv_bfloat16 g_hl[(size_t)KM * KI];   // h lo

// ---------------- PTX helpers ----------------------------------------------
__device__ __forceinline__ uint32_t smem_u32(const void* p) {
    return (uint32_t)__cvta_generic_to_shared(p);
}
__device__ __forceinline__ void cp16(uint32_t dst, const void* src) {
    asm volatile("cp.async.cg.shared.global [%0], [%1], 16;" :: "r"(dst), "l"(src));
}
__device__ __forceinline__ void cp_commit() { asm volatile("cp.async.commit_group;"); }
__device__ __forceinline__ void cp_wait0()  { asm volatile("cp.async.wait_group 0;"); }
__device__ __forceinline__ void cp_wait1()  { asm volatile("cp.async.wait_group 1;"); }
__device__ __forceinline__ void cp_wait2()  { asm volatile("cp.async.wait_group 2;"); }

#if TC_OK
__device__ __forceinline__ bool elect1() {
    uint32_t p;
    asm volatile("{\n\t.reg .pred p;\n\telect.sync _|p, 0xFFFFFFFF;\n\t"
                 "selp.b32 %0, 1, 0, p;\n\t}" : "=r"(p));
    return p != 0;
}
__device__ __forceinline__ uint32_t ctarank() {
    uint32_t r; asm("mov.u32 %0, %%cluster_ctarank;" : "=r"(r)); return r;
}

#define TC_ALLOC2(sa, n)  asm volatile("tcgen05.alloc.cta_group::2.sync.aligned.shared::cta.b32 [%0], %1;" :: "r"(sa), "r"(n) : "memory")
#define TC_DEALLOC2(t, n) asm volatile("tcgen05.dealloc.cta_group::2.sync.aligned.b32 %0, %1;" :: "r"(t), "r"(n))
#define TC_RELINQ2()      asm volatile("tcgen05.relinquish_alloc_permit.cta_group::2.sync.aligned;")
#define TC_COMMIT_MC2(mb, mask) asm volatile("tcgen05.commit.cta_group::2.mbarrier::arrive::one.shared::cluster.multicast::cluster.b64 [%0], %1;" :: "r"(mb), "h"((uint16_t)(mask)) : "memory")
#define TC_WAIT_LD()      asm volatile("tcgen05.wait::ld.sync.aligned;" ::: "memory")
#define TC_FENCE_AFTER()  asm volatile("tcgen05.fence::after_thread_sync;" ::: "memory")
#define FENCE_ASYNC()     asm volatile("fence.proxy.async.shared::cta;" ::: "memory")
#define MBAR_INIT(a, c)   asm volatile("mbarrier.init.shared.b64 [%0], %1;" :: "r"(a), "r"(c) : "memory")
#define CLUSTER_SYNC() do { \
    asm volatile("barrier.cluster.arrive.aligned;" ::: "memory"); \
    asm volatile("barrier.cluster.wait.aligned;"   ::: "memory"); } while (0)

// arrive on the mbarrier at the same SMEM offset in cluster CTA `rank`
__device__ __forceinline__ void mbar_arrive_cluster(uint32_t addr, uint32_t rank) {
    asm volatile("{\n\t.reg .b32 ra;\n\tmapa.shared::cluster.u32 ra, %0, %1;\n\t"
                 "mbarrier.arrive.shared::cluster.b64 _, [ra];\n\t}"
                 :: "r"(addr), "r"(rank) : "memory");
}

// local wait, cta-scope acquire (for done barriers: local data)
#define MBAR_WAIT(mb, ph) do {                                                    \
    uint32_t _m = (mb), _p = (uint32_t)(ph), _d;                                  \
    asm volatile("{\n\t.reg .pred p;\n\t"                                         \
        "mbarrier.try_wait.parity.acquire.cta.shared::cta.b64 p, [%1], %2;\n\t"   \
        "selp.b32 %0, 1, 0, p;\n\t}" : "=r"(_d) : "r"(_m), "r"(_p) : "memory");   \
    if (!_d) {                                                                    \
        asm volatile("{\n\t.reg .pred P1;\n\tWL_%=:\n\t"                          \
            "mbarrier.try_wait.parity.acquire.cta.shared::cta.b64 P1, [%0], %1, 0x989680;\n\t" \
            "@P1 bra.uni WD_%=;\n\tbra.uni WL_%=;\n\tWD_%=:\n\t}"                 \
            :: "r"(_m), "r"(_p) : "memory");                                      \
    }                                                                             \
} while (0)

// cluster-scope acquire wait (for ready barriers: peer SMEM data)
#define MBAR_WAIT_CL(mb, ph) do {                                                 \
    uint32_t _m = (mb), _p = (uint32_t)(ph), _d;                                  \
    asm volatile("{\n\t.reg .pred p;\n\t"                                         \
        "mbarrier.try_wait.parity.acquire.cluster.shared::cta.b64 p, [%1], %2;\n\t" \
        "selp.b32 %0, 1, 0, p;\n\t}" : "=r"(_d) : "r"(_m), "r"(_p) : "memory");   \
    if (!_d) {                                                                    \
        asm volatile("{\n\t.reg .pred P1;\n\tWL_%=:\n\t"                          \
            "mbarrier.try_wait.parity.acquire.cluster.shared::cta.b64 P1, [%0], %1, 0x989680;\n\t" \
            "@P1 bra.uni WD_%=;\n\tbra.uni WL_%=;\n\tWD_%=:\n\t}"                 \
            :: "r"(_m), "r"(_p) : "memory");                                      \
    }                                                                             \
} while (0)

#define LDTM32(r, ta)                                                             \
    asm volatile("tcgen05.ld.sync.aligned.32x32b.x32.b32 "                        \
        "{%0,%1,%2,%3,%4,%5,%6,%7,%8,%9,%10,%11,%12,%13,%14,%15,"                 \
        "%16,%17,%18,%19,%20,%21,%22,%23,%24,%25,%26,%27,%28,%29,%30,%31},[%32];" \
        : "=r"((r)[0]),"=r"((r)[1]),"=r"((r)[2]),"=r"((r)[3]),                    \
          "=r"((r)[4]),"=r"((r)[5]),"=r"((r)[6]),"=r"((r)[7]),                    \
          "=r"((r)[8]),"=r"((r)[9]),"=r"((r)[10]),"=r"((r)[11]),                  \
          "=r"((r)[12]),"=r"((r)[13]),"=r"((r)[14]),"=r"((r)[15]),                \
          "=r"((r)[16]),"=r"((r)[17]),"=r"((r)[18]),"=r"((r)[19]),                \
          "=r"((r)[20]),"=r"((r)[21]),"=r"((r)[22]),"=r"((r)[23]),                \
          "=r"((r)[24]),"=r"((r)[25]),"=r"((r)[26]),"=r"((r)[27]),                \
          "=r"((r)[28]),"=r"((r)[29]),"=r"((r)[30]),"=r"((r)[31])                 \
        : "r"(ta))

__device__ __forceinline__ uint64_t sdesc(uint32_t addr) {
    // SW128, version=1(Blackwell), SBO=64 (1024B row-group), LBO=1 (16B)
    return 0x4000404000010000ULL | (uint64_t)((addr >> 4) & 0x3FFF);
}

// cta_group::2 bf16 SS MMA; 8-element disable-lane vector (all zero)
__device__ __forceinline__ void mma2(uint32_t d, uint64_t a, uint64_t b,
                                     uint32_t idesc, bool acc) {
    uint32_t en = acc ? 1u : 0u;
    asm volatile("{\n\t.reg .pred p;\n\tsetp.ne.u32 p, %5, 0;\n\t"
        "tcgen05.mma.cta_group::2.kind::f16 [%0], %1, %2, %3, "
        "{%4,%4,%4,%4,%4,%4,%4,%4}, p;\n\t}"
        :: "r"(d), "l"(a), "l"(b), "r"(idesc), "r"(0u), "r"(en) : "memory");
}

// idesc: F32 accum, BF16 a/b, N=256, M=256 (cg2 pair)
#define IDESC2 ((1u << 4) | (1u << 7) | (1u << 10) | ((256u / 8) << 17) | ((256u / 16) << 24))
#endif // TC_OK

// ---------------- pre-pass kernels ------------------------------------------
__global__ void __launch_bounds__(256) wconv(const int* __restrict__ w, int sel, long n4) {
    __nv_bfloat16* o = (sel == 0) ? g_wg : (sel == 1) ? g_wu : g_wd;
    long i = blockIdx.x * (long)blockDim.x + threadIdx.x;
    long stride = (long)gridDim.x * blockDim.x;
    for (; i < n4; i += stride) {
        int4 v = ((const int4*)w)[i];
        __nv_bfloat162 p0, p1;
        p0.x = __float2bfloat16((float)v.x); p0.y = __float2bfloat16((float)v.y);
        p1.x = __float2bfloat16((float)v.z); p1.y = __float2bfloat16((float)v.w);
        ((__nv_bfloat162*)o)[2 * i]     = p0;
        ((__nv_bfloat162*)o)[2 * i + 1] = p1;
    }
}

__global__ void __launch_bounds__(256) xsplit(const float* __restrict__ x, long n4) {
    long i = blockIdx.x * (long)blockDim.x + threadIdx.x;
    long stride = (long)gridDim.x * blockDim.x;
    for (; i < n4; i += stride) {
        float4 v = ((const float4*)x)[i];
        __nv_bfloat162 h0, h1, l0, l1;
        h0.x = __float2bfloat16(v.x); l0.x = __float2bfloat16(v.x - __bfloat162float(h0.x));
        h0.y = __float2bfloat16(v.y); l0.y = __float2bfloat16(v.y - __bfloat162float(h0.y));
        h1.x = __float2bfloat16(v.z); l1.x = __float2bfloat16(v.z - __bfloat162float(h1.x));
        h1.y = __float2bfloat16(v.w); l1.y = __float2bfloat16(v.w - __bfloat162float(h1.y));
        ((__nv_bfloat162*)g_xh)[2 * i] = h0; ((__nv_bfloat162*)g_xh)[2 * i + 1] = h1;
        ((__nv_bfloat162*)g_xl)[2 * i] = l0; ((__nv_bfloat162*)g_xl)[2 * i + 1] = l1;
    }
}

// ---------------- GEMM kernels: cg2 pair = M 256, 3-stage pipeline ----------
// Stage layout (64 KB): [A_hi 16K][A_lo 16K][B0 16K][B1 16K]
//   k1: B0 = gate half (128 rows), B1 = up half       (N tile = 256)
//   k2: B0 = down rows n..+128 of j=0, B1 = j=1 chunk (N tile = 512)
#define SST      65536
#define NSTG     3
#define GSMEM    (NSTG * SST + 1024)

#define K1_NC   (KD / 64)                // 64 chunks
#define K2_NC   (KI / 64)                // 172 chunks

extern __shared__ char dsm[];

#if TC_OK
// shared mainloop: drives 3-stage cp.async pipeline + cg2 MMA handshake.
// issueFn(c, stageAddr) issues cp.async for chunk c; mmaFn(c, stageAddr) = 16 mma2.
template <int NC, class IssueF, class MmaF>
__device__ __forceinline__ void cg2_mainloop(
    uint32_t rank, int t, int wid,
    uint32_t mb_done0, uint32_t mb_rdy0,   // 3 each, stride 8 bytes
    IssueF issueFn, MmaF mmaFn)
{
    uint32_t phd = 0, phr = 0;             // phase bits per stage
    issueFn(0, 0); cp_commit();
    issueFn(1, 1); cp_commit();
    for (int c = 0; c < NC; ++c) {
        const int s = c % 3;
        if (c + 2 < NC) {
            const int ns = (c + 2) % 3;    // == (c-1)%3
            if (c >= 1) {
                MBAR_WAIT(mb_done0 + ns * 8, (phd >> ns) & 1);
                phd ^= 1u << ns;
            }
            issueFn(c + 2, ns); cp_commit();
            cp_wait2();
        } else if (c + 1 < NC) {
            cp_wait1();
        } else {
            cp_wait0();
        }
        __syncthreads();
        if (t == 0) {
            FENCE_ASYNC();
            mbar_arrive_cluster(mb_rdy0 + s * 8, 0);   // publish to leader
        }
        if (rank == 0 && wid == 0) {
            MBAR_WAIT_CL(mb_rdy0 + s * 8, (phr >> s) & 1);
            phr ^= 1u << s;
            if (elect1()) {
                mmaFn(c, s);
                TC_COMMIT_MC2(mb_done0 + s * 8, 0x3);
            }
        }
    }
    // final chunk used stage (NC-1)%3
    const int ls = (NC - 1) % 3;
    MBAR_WAIT(mb_done0 + ls * 8, (phd >> ls) & 1);
    TC_FENCE_AFTER();
}
#endif

// ---------------- K1: fused gate+up, M=256 pair x N=256 ----------------------
__global__ void __launch_bounds__(256, 1) __cluster_dims__(2, 1, 1)
k1(const float* __restrict__ gs_p, const float* __restrict__ us_p)
{
#if TC_OK
    const int t = threadIdx.x, wid = t >> 5, lane = t & 31;
    const uint32_t rank = ctarank();
    const int n0 = blockIdx.y * 256;
    const int m0 = (blockIdx.z * 2 + (int)rank) * 128;
    const uint32_t sb = (smem_u32(dsm) + 1023u) & ~1023u;

    __shared__ uint32_t s_tm[1];
    __shared__ alignas(8) uint64_t s_mb[6];   // done[3], rdy[3]

    if (wid == 0) TC_ALLOC2(smem_u32(s_tm), 512);
    if (t == 0) {
#pragma unroll
        for (int i = 0; i < 3; ++i) {
            MBAR_INIT(smem_u32(&s_mb[i]), 1);       // done: commit multicast
            MBAR_INIT(smem_u32(&s_mb[3 + i]), 2);   // rdy: one arrive per CTA
        }
    }
    __syncthreads();
    CLUSTER_SYNC();                                  // mbars visible cluster-wide
    uint32_t tm;
    asm volatile("ld.shared.b32 %0, [%1];" : "=r"(tm) : "r"(smem_u32(s_tm)));

    const int c16 = t & 7;
    const int r0  = t >> 3;                          // 0..31
    const uint32_t swc = (uint32_t)((c16 ^ (r0 & 7)) * 16);
    const __nv_bfloat16* pxh = g_xh + (size_t)(m0 + r0) * KD + c16 * 8;
    const __nv_bfloat16* pxl = g_xl + (size_t)(m0 + r0) * KD + c16 * 8;
    // each CTA loads its N/2 = 128 rows of gate and up
    const __nv_bfloat16* pbg = g_wg + (size_t)(n0 + rank * 128 + r0) * KD + c16 * 8;
    const __nv_bfloat16* pbu = g_wu + (size_t)(n0 + rank * 128 + r0) * KD + c16 * 8;

    auto issueFn = [&](int c, int s) {
        const int k0 = c * 64;
        const uint32_t st = sb + s * SST;
#pragma unroll
        for (int i = 0; i < 4; ++i) {
            const uint32_t d = (uint32_t)((r0 + 32 * i) * 128) + swc;
            cp16(st + d,         pxh + (size_t)(32 * i) * KD + k0);
            cp16(st + 16384 + d, pxl + (size_t)(32 * i) * KD + k0);
            cp16(st + 32768 + d, pbg + (size_t)(32 * i) * KD + k0);
            cp16(st + 49152 + d, pbu + (size_t)(32 * i) * KD + k0);
        }
    };
    auto mmaFn = [&](int c, int s) {
        const uint32_t st = sb + s * SST;
        const uint64_t da = sdesc(st), dl = sdesc(st + 16384);
        const uint64_t dg = sdesc(st + 32768), du = sdesc(st + 49152);
#pragma unroll
        for (int k = 0; k < 4; ++k) {
            const bool acc = (c > 0) || (k > 0);
            mma2(tm,       da + 2 * k, dg + 2 * k, IDESC2, acc);
            mma2(tm + 256, da + 2 * k, du + 2 * k, IDESC2, acc);
        }
#pragma unroll
        for (int k = 0; k < 4; ++k) {
            mma2(tm,       dl + 2 * k, dg + 2 * k, IDESC2, true);
            mma2(tm + 256, dl + 2 * k, du + 2 * k, IDESC2, true);
        }
    };

    cg2_mainloop<K1_NC>(rank, t, wid, smem_u32(&s_mb[0]), smem_u32(&s_mb[3]),
                        issueFn, mmaFn);

    // epilogue: this CTA's TMEM holds its own 128 rows x (gate 256 | up 256)
    const float gsc = gs_p[0], usc = us_p[0];
    const int m = m0 + (wid & 3) * 32 + lane;
    const int cb0 = (wid >> 2) * 4;
#pragma unroll 1
    for (int cb = cb0; cb < cb0 + 4; ++cb) {
        uint32_t rg[32], ru[32];
        LDTM32(rg, tm + cb * 32);
        LDTM32(ru, tm + 256 + cb * 32);
        TC_WAIT_LD();
        alignas(16) ushort oh[32], ol[32];
#pragma unroll
        for (int j = 0; j < 32; ++j) {
            const float g = __uint_as_float(rg[j]) * gsc;
            const float u = __uint_as_float(ru[j]) * usc;
            const float v = (g / (1.0f + __expf(-g))) * u;
            const __nv_bfloat16 hh = __float2bfloat16(v);
            const __nv_bfloat16 hl = __float2bfloat16(v - __bfloat162float(hh));
            oh[j] = *(const ushort*)&hh;
            ol[j] = *(const ushort*)&hl;
        }
        const size_t off = ((size_t)m * KI + n0 + cb * 32) * 2;
#pragma unroll
        for (int q = 0; q < 4; ++q) {
            *(uint4*)((char*)g_hh + off + q * 16) = *(uint4*)&oh[q * 8];
            *(uint4*)((char*)g_hl + off + q * 16) = *(uint4*)&ol[q * 8];
        }
    }
    __syncthreads();
    if (wid == 0) { TC_RELINQ2(); TC_DEALLOC2(tm, 512); }
    CLUSTER_SYNC();   // no CTA exits while peer may still read its SMEM

#else  // SIMT fallback (never runs on GB300)
    const int t = threadIdx.x;
    const int n0 = blockIdx.y * 256;
    const int m0 = (blockIdx.z * 2 + blockIdx.x) * 128;
    float* sA = (float*)dsm;
    float* sB = (float*)(dsm + 32 * 132 * 4);
    const float gsc = gs_p[0], usc = us_p[0];
    const int tx = t & 7, ty = (t >> 3) & 15;
    for (int ns = 0; ns < 4; ++ns) {
        const int nb = n0 + ns * 64;
        float ag[8][8], au[8][8];
#pragma unroll
        for (int i = 0; i < 8; ++i)
#pragma unroll
            for (int j = 0; j < 8; ++j) { ag[i][j] = 0.f; au[i][j] = 0.f; }
        for (int pass = 0; pass < 2; ++pass) {
            const __nv_bfloat16* W = pass ? g_wu : g_wg;
            float (*acc)[8] = pass ? au : ag;
            for (int k0 = 0; k0 < KD; k0 += 32) {
                for (int i = t; i < 128 * 32; i += blockDim.x) {
                    int r = i >> 5, c = i & 31;
                    sA[c * 132 + r] = __bfloat162float(g_xh[(size_t)(m0 + r) * KD + k0 + c])
                                    + __bfloat162float(g_xl[(size_t)(m0 + r) * KD + k0 + c]);
                }
                for (int i = t; i < 64 * 32; i += blockDim.x) {
                    int r = i >> 5, c = i & 31;
                    sB[c * 68 + r] = __bfloat162float(W[(size_t)(nb + r) * KD + k0 + c]);
                }
                __syncthreads();
                for (int k = 0; k < 32; ++k) {
                    float a[8], w[8];
#pragma unroll
                    for (int i = 0; i < 8; ++i) a[i] = sA[k * 132 + ty * 8 + i];
#pragma unroll
                    for (int j = 0; j < 8; ++j) w[j] = sB[k * 68 + tx * 8 + j];
#pragma unroll
                    for (int i = 0; i < 8; ++i)
#pragma unroll
                        for (int j = 0; j < 8; ++j)
                            acc[i][j] = fmaf(a[i], w[j], acc[i][j]);
                }
                __syncthreads();
            }
        }
#pragma unroll
        for (int i = 0; i < 8; ++i)
#pragma unroll
            for (int j = 0; j < 8; ++j) {
                const float g = ag[i][j] * gsc;
                const float v = (g / (1.0f + __expf(-g))) * (au[i][j] * usc);
                const __nv_bfloat16 hh = __float2bfloat16(v);
                const __nv_bfloat16 hl = __float2bfloat16(v - __bfloat162float(hh));
                const size_t o = (size_t)(m0 + ty * 8 + i) * KI + nb + tx * 8 + j;
                g_hh[o] = hh; g_hl[o] = hl;
            }
        __syncthreads();
    }
#endif
}

// ---------------- K2: down GEMM, M=256 pair x N=512 --------------------------
__global__ void __launch_bounds__(256, 1) __cluster_dims__(2, 1, 1)
k2(const float* __restrict__ ds_p, float* __restrict__ out)
{
#if TC_OK
    const int t = threadIdx.x, wid = t >> 5, lane = t & 31;
    const uint32_t rank = ctarank();
    const int n0 = blockIdx.y * 512;
    const int m0 = (blockIdx.z * 2 + (int)rank) * 128;
    const uint32_t sb = (smem_u32(dsm) + 1023u) & ~1023u;

    __shared__ uint32_t s_tm[1];
    __shared__ alignas(8) uint64_t s_mb[6];

    if (wid == 0) TC_ALLOC2(smem_u32(s_tm), 512);
    if (t == 0) {
#pragma unroll
        for (int i = 0; i < 3; ++i) {
            MBAR_INIT(smem_u32(&s_mb[i]), 1);
            MBAR_INIT(smem_u32(&s_mb[3 + i]), 2);
        }
    }
    __syncthreads();
    CLUSTER_SYNC();
    uint32_t tm;
    asm volatile("ld.shared.b32 %0, [%1];" : "=r"(tm) : "r"(smem_u32(s_tm)));

    const int c16 = t & 7;
    const int r0  = t >> 3;
    const uint32_t swc = (uint32_t)((c16 ^ (r0 & 7)) * 16);
    const __nv_bfloat16* pah = g_hh + (size_t)(m0 + r0) * KI + c16 * 8;
    const __nv_bfloat16* pal = g_hl + (size_t)(m0 + r0) * KI + c16 * 8;
    // N=512 tile as two N=256 sub-MMAs; CTA rank r holds rows n0+j*256+r*128
    const __nv_bfloat16* pb0 = g_wd + (size_t)(n0 +       rank * 128 + r0) * KI + c16 * 8;
    const __nv_bfloat16* pb1 = g_wd + (size_t)(n0 + 256 + rank * 128 + r0) * KI + c16 * 8;

    auto issueFn = [&](int c, int s) {
        const int k0 = c * 64;
        const uint32_t st = sb + s * SST;
#pragma unroll
        for (int i = 0; i < 4; ++i) {
            const uint32_t d = (uint32_t)((r0 + 32 * i) * 128) + swc;
            cp16(st + d,         pah + (size_t)(32 * i) * KI + k0);
            cp16(st + 16384 + d, pal + (size_t)(32 * i) * KI + k0);
            cp16(st + 32768 + d, pb0 + (size_t)(32 * i) * KI + k0);
            cp16(st + 49152 + d, pb1 + (size_t)(32 * i) * KI + k0);
        }
    };
    auto mmaFn = [&](int c, int s) {
        const uint32_t st = sb + s * SST;
        const uint64_t da = sdesc(st), dl = sdesc(st + 16384);
        const uint64_t d0 = sdesc(st + 32768), d1 = sdesc(st + 49152);
#pragma unroll
        for (int k = 0; k < 4; ++k) {
            const bool acc = (c > 0) || (k > 0);
            mma2(tm,       da + 2 * k, d0 + 2 * k, IDESC2, acc);
            mma2(tm + 256, da + 2 * k, d1 + 2 * k, IDESC2, acc);
        }
#pragma unroll
        for (int k = 0; k < 4; ++k) {
            mma2(tm,       dl + 2 * k, d0 + 2 * k, IDESC2, true);
            mma2(tm + 256, dl + 2 * k, d1 + 2 * k, IDESC2, true);
        }
    };

    cg2_mainloop<K2_NC>(rank, t, wid, smem_u32(&s_mb[0]), smem_u32(&s_mb[3]),
                        issueFn, mmaFn);

    // epilogue: 512 cols fp32 for this CTA's 128 rows
    const float dsc = ds_p[0];
    const int m = m0 + (wid & 3) * 32 + lane;
    const int cb0 = (wid >> 2) * 8;
#pragma unroll 1
    for (int cb = cb0; cb < cb0 + 8; ++cb) {
        uint32_t r[32];
        LDTM32(r, tm + cb * 32);
        TC_WAIT_LD();
        float* p = out + (size_t)m * KD + n0 + cb * 32;
#pragma unroll
        for (int q = 0; q < 8; ++q) {
            float4 v;
            v.x = __uint_as_float(r[q * 4 + 0]) * dsc;
            v.y = __uint_as_float(r[q * 4 + 1]) * dsc;
            v.z = __uint_as_float(r[q * 4 + 2]) * dsc;
            v.w = __uint_as_float(r[q * 4 + 3]) * dsc;
            *(float4*)(p + q * 4) = v;
        }
    }
    __syncthreads();
    if (wid == 0) { TC_RELINQ2(); TC_DEALLOC2(tm, 512); }
    CLUSTER_SYNC();

#else  // SIMT fallback
    const int t = threadIdx.x;
    const int n0 = blockIdx.y * 512;
    const int m0 = (blockIdx.z * 2 + blockIdx.x) * 128;
    float* sA = (float*)dsm;
    float* sB = (float*)(dsm + 32 * 132 * 4);
    const float dsc = ds_p[0];
    const int tx = t & 7, ty = (t >> 3) & 15;
    for (int ns = 0; ns < 8; ++ns) {
        const int nb = n0 + ns * 64;
        float acc[8][8];
#pragma unroll
        for (int i = 0; i < 8; ++i)
#pragma unroll
            for (int j = 0; j < 8; ++j) acc[i][j] = 0.f;
        for (int k0 = 0; k0 < KI; k0 += 32) {
            for (int i = t; i < 128 * 32; i += blockDim.x) {
                int r = i >> 5, c = i & 31;
                sA[c * 132 + r] = __bfloat162float(g_hh[(size_t)(m0 + r) * KI + k0 + c])
                                + __bfloat162float(g_hl[(size_t)(m0 + r) * KI + k0 + c]);
            }
            for (int i = t; i < 64 * 32; i += blockDim.x) {
                int r = i >> 5, c = i & 31;
                sB[c * 68 + r] = __bfloat162float(g_wd[(size_t)(nb + r) * KI + k0 + c]);
            }
            __syncthreads();
            for (int k = 0; k < 32; ++k) {
                float a[8], w[8];
#pragma unroll
                for (int i = 0; i < 8; ++i) a[i] = sA[k * 132 + ty * 8 + i];
#pragma unroll
                for (int j = 0; j < 8; ++j) w[j] = sB[k * 68 + tx * 8 + j];
#pragma unroll
                for (int i = 0; i < 8; ++i)
#pragma unroll
                    for (int j = 0; j < 8; ++j)
                        acc[i][j] = fmaf(a[i], w[j], acc[i][j]);
            }
            __syncthreads();
        }
#pragma unroll
        for (int i = 0; i < 8; ++i)
#pragma unroll
            for (int j = 0; j < 8; ++j)
                out[(size_t)(m0 + ty * 8 + i) * KD + nb + tx * 8 + j] = acc[i][j] * dsc;
        __syncthreads();
    }
#endif
}

// ---------------- launch ------------------------------------------------------
extern "C" void kernel_launch(void* const* d_in, const int* in_sizes, int n_in,
                              void* d_out, int out_size)
{
    const float* x  = (const float*)d_in[0];
    const int*   gw = (const int*)  d_in[1];
    const float* gs = (const float*)d_in[2];
    const int*   uw = (const int*)  d_in[3];
    const float* us = (const float*)d_in[4];
    const int*   dw = (const int*)  d_in[5];
    const float* ds = (const float*)d_in[6];
    float* out = (float*)d_out;

    cudaFuncSetAttribute(k1, cudaFuncAttributeMaxDynamicSharedMemorySize, GSMEM);
    cudaFuncSetAttribute(k2, cudaFuncAttributeMaxDynamicSharedMemorySize, GSMEM);

    const long nw4 = (long)KI * KD / 4;
    wconv<<<4096, 256>>>(gw, 0, nw4);
    wconv<<<4096, 256>>>(uw, 1, nw4);
    wconv<<<4096, 256>>>(dw, 2, nw4);
    xsplit<<<4096, 256>>>(x, (long)KM * KD / 4);

    // cluster (2,1,1) along x; x = rank within the M-pair
    k1<<<dim3(2, KI / 256, KM / 256), 256, GSMEM>>>(gs, us);
    k2<<<dim3(2, KD / 512, KM / 256), 256, GSMEM>>>(ds, out);
}